// round 9
// baseline (speedup 1.0000x reference)
#include <cuda_runtime.h>
#include <cstdint>

// ---------------------------------------------------------------------------
// MultiheadAttention  B=4, S=2048, D=1024, H=16, hd=64, causal, fp32.
// R9 = R8 resubmit (container infra failure):
//   GEMM warp tile 64x32 -> 64x64 (4 warps/CTA, 1.0 LDS+cvt per mma).
//   Flash attention kernel unchanged from R7 (972.8us baseline).
// ---------------------------------------------------------------------------

#define D_MODEL 1024
#define NUM_HEAD 16
#define HID_DIM 64
#define BATCH 4
#define SEQ 2048
#define MROWS (BATCH * SEQ)   // 8192

__device__ float g_q[(size_t)MROWS * D_MODEL];
__device__ float g_k[(size_t)MROWS * D_MODEL];
__device__ float g_v[(size_t)MROWS * D_MODEL];
__device__ float g_a[(size_t)MROWS * D_MODEL];

__device__ __forceinline__ uint32_t f2tf32(float f) {
    uint32_t r;
    asm volatile("cvt.rna.tf32.f32 %0, %1;" : "=r"(r) : "f"(f));
    return r;
}
__device__ __forceinline__ void cp_async16(uint32_t saddr, const void* gptr) {
    asm volatile("cp.async.cg.shared.global [%0], [%1], 16;\n" :: "r"(saddr), "l"(gptr));
}
__device__ __forceinline__ void cp_commit() {
    asm volatile("cp.async.commit_group;\n");
}
__device__ __forceinline__ void mma_tf32(
    float& d0, float& d1, float& d2, float& d3,
    uint32_t a0, uint32_t a1, uint32_t a2, uint32_t a3,
    uint32_t b0, uint32_t b1)
{
    asm volatile(
        "mma.sync.aligned.m16n8k8.row.col.f32.tf32.tf32.f32 "
        "{%0,%1,%2,%3}, {%4,%5,%6,%7}, {%8,%9}, {%0,%1,%2,%3};\n"
        : "+f"(d0), "+f"(d1), "+f"(d2), "+f"(d3)
        : "r"(a0), "r"(a1), "r"(a2), "r"(a3), "r"(b0), "r"(b1));
}

// ---------------------------------------------------------------------------
// tf32 GEMM: C[M,N] = A[M,K] @ W[N,K]^T + bias
// 128x128 CTA tile, BK=16, 128 threads (4 warps, 2x2), 64x64 warp tile.
// ---------------------------------------------------------------------------
#define BM 128
#define BN 128
#define BK 16
#define LDK 20
#define GTHREADS 128
#define KTILES (D_MODEL / BK)

__global__ __launch_bounds__(GTHREADS) void gemm_tf32_kernel(
    const float* __restrict__ A0, const float* __restrict__ W0,
    const float* __restrict__ b0, float* __restrict__ C0,
    const float* __restrict__ A1, const float* __restrict__ W1,
    const float* __restrict__ b1, float* __restrict__ C1,
    const float* __restrict__ A2, const float* __restrict__ W2,
    const float* __restrict__ b2, float* __restrict__ C2)
{
    __shared__ float As[2][BM][LDK];
    __shared__ float Ws[2][BN][LDK];

    const float* A; const float* W; const float* bias; float* C;
    if (blockIdx.z == 0)      { A = A0; W = W0; bias = b0; C = C0; }
    else if (blockIdx.z == 1) { A = A1; W = W1; bias = b1; C = C1; }
    else                      { A = A2; W = W2; bias = b2; C = C2; }

    const int tid  = threadIdx.x;
    const int row0 = blockIdx.y * BM;
    const int col0 = blockIdx.x * BN;
    const int K    = D_MODEL, N = D_MODEL;

    const int wid    = tid >> 5;
    const int lane   = tid & 31;
    const int warp_m = (wid & 1) * 64;   // 2 warps along M
    const int warp_n = (wid >> 1) * 64;  // 2 warps along N
    const int grp    = lane >> 2;
    const int qid    = lane & 3;
    const int lr     = tid >> 2;         // 0..31 (4 rows each: +0,32,64,96)
    const int lc     = (tid & 3) << 2;

    float acc[4][8][4];
    #pragma unroll
    for (int i = 0; i < 4; i++)
        #pragma unroll
        for (int j = 0; j < 8; j++)
            #pragma unroll
            for (int c = 0; c < 4; c++) acc[i][j][c] = 0.f;

    auto load_stage = [&](int st, int k0) {
        #pragma unroll
        for (int h = 0; h < 4; h++) {
            int r = lr + h * 32;
            cp_async16((uint32_t)__cvta_generic_to_shared(&As[st][r][lc]),
                       &A[(size_t)(row0 + r) * K + k0 + lc]);
            cp_async16((uint32_t)__cvta_generic_to_shared(&Ws[st][r][lc]),
                       &W[(size_t)(col0 + r) * K + k0 + lc]);
        }
        cp_commit();
    };

    load_stage(0, 0);

    for (int t = 0; t < KTILES; t++) {
        const int st = t & 1;
        if (t + 1 < KTILES) {
            load_stage(st ^ 1, (t + 1) * BK);
            asm volatile("cp.async.wait_group 1;\n");
        } else {
            asm volatile("cp.async.wait_group 0;\n");
        }
        __syncthreads();

        #pragma unroll
        for (int ks = 0; ks < BK; ks += 8) {
            uint32_t af[4][4], bf[8][2];
            #pragma unroll
            for (int i = 0; i < 4; i++) {
                int r = warp_m + i * 16 + grp;
                af[i][0] = f2tf32(As[st][r    ][ks + qid    ]);
                af[i][1] = f2tf32(As[st][r + 8][ks + qid    ]);
                af[i][2] = f2tf32(As[st][r    ][ks + qid + 4]);
                af[i][3] = f2tf32(As[st][r + 8][ks + qid + 4]);
            }
            #pragma unroll
            for (int j = 0; j < 8; j++) {
                int n = warp_n + j * 8 + grp;
                bf[j][0] = f2tf32(Ws[st][n][ks + qid    ]);
                bf[j][1] = f2tf32(Ws[st][n][ks + qid + 4]);
            }
            #pragma unroll
            for (int i = 0; i < 4; i++)
                #pragma unroll
                for (int j = 0; j < 8; j++)
                    mma_tf32(acc[i][j][0], acc[i][j][1], acc[i][j][2], acc[i][j][3],
                             af[i][0], af[i][1], af[i][2], af[i][3],
                             bf[j][0], bf[j][1]);
        }
        __syncthreads();
    }

    #pragma unroll
    for (int i = 0; i < 4; i++) {
        int r = row0 + warp_m + i * 16 + grp;
        #pragma unroll
        for (int j = 0; j < 8; j++) {
            int cidx = col0 + warp_n + j * 8 + qid * 2;
            float bx = bias[cidx], by = bias[cidx + 1];
            float2 o0 = make_float2(acc[i][j][0] + bx, acc[i][j][1] + by);
            float2 o1 = make_float2(acc[i][j][2] + bx, acc[i][j][3] + by);
            *reinterpret_cast<float2*>(&C[(size_t)r * N + cidx])       = o0;
            *reinterpret_cast<float2*>(&C[(size_t)(r + 8) * N + cidx]) = o1;
        }
    }
}

// ---------------------------------------------------------------------------
// Tensor-core flash attention (causal, tf32 mma).  Unchanged from R7.
// CTA: 256 threads = 8 warps; 128 q-rows per CTA, 16 per warp.
// ---------------------------------------------------------------------------
#define FQ 128
#define FK 64
#define LDS_STRIDE 68
#define KV_WORDS (2 * FK * LDS_STRIDE)
#define PS_WORDS (8 * 16 * LDS_STRIDE)
#define FLASH_SMEM_BYTES ((2 * KV_WORDS + PS_WORDS) * 4)   // 104448

__global__ __launch_bounds__(256, 1) void flash_attn_tc_kernel(
    const float* __restrict__ q, const float* __restrict__ k,
    const float* __restrict__ v, float* __restrict__ o)
{
    extern __shared__ float sm[];
    float* Ks = sm;                       // [2][FK][LDS_STRIDE]
    float* Vs = sm + KV_WORDS;            // [2][FK][LDS_STRIDE]
    float* Ps = sm + 2 * KV_WORDS;        // [8][16][LDS_STRIDE]

    const int qt  = blockIdx.x;
    const int h   = blockIdx.y;
    const int b   = blockIdx.z;
    const int tid = threadIdx.x;
    const int w   = tid >> 5;
    const int lane = tid & 31;
    const int grp = lane >> 2;
    const int qid = lane & 3;

    const int q0 = qt * FQ;
    const size_t base = (size_t)b * SEQ * D_MODEL + (size_t)h * HID_DIM;
    const int wrow0 = q0 + w * 16;
    const int wlast = wrow0 + 15;

    uint32_t qf[8][4];
    {
        const float* Qp = q + base + (size_t)wrow0 * D_MODEL;
        #pragma unroll
        for (int ks = 0; ks < 8; ks++) {
            int c = ks * 8 + qid;
            qf[ks][0] = f2tf32(0.125f * Qp[(size_t)grp       * D_MODEL + c]);
            qf[ks][1] = f2tf32(0.125f * Qp[(size_t)(grp + 8) * D_MODEL + c]);
            qf[ks][2] = f2tf32(0.125f * Qp[(size_t)grp       * D_MODEL + c + 4]);
            qf[ks][3] = f2tf32(0.125f * Qp[(size_t)(grp + 8) * D_MODEL + c + 4]);
        }
    }

    float oacc[8][4];
    #pragma unroll
    for (int j = 0; j < 8; j++)
        #pragma unroll
        for (int c = 0; c < 4; c++) oacc[j][c] = 0.f;
    float m0 = -1e30f, m1 = -1e30f, l0 = 0.f, l1 = 0.f;

    float* Pw = Ps + w * 16 * LDS_STRIDE;
    const int nt = 2 * (qt + 1);

    auto load_tile = [&](int st, int kb) {
        float* Kd = Ks + st * FK * LDS_STRIDE;
        float* Vd = Vs + st * FK * LDS_STRIDE;
        #pragma unroll
        for (int i = 0; i < 4; i++) {
            int idx = tid + (i << 8);
            int r   = idx >> 4;
            int c   = (idx & 15) << 2;
            const size_t goff = base + (size_t)(kb + r) * D_MODEL + c;
            cp_async16((uint32_t)__cvta_generic_to_shared(&Kd[r * LDS_STRIDE + c]), &k[goff]);
            cp_async16((uint32_t)__cvta_generic_to_shared(&Vd[r * LDS_STRIDE + c]), &v[goff]);
        }
        cp_commit();
    };

    load_tile(0, 0);

    for (int t = 0; t < nt; t++) {
        const int st = t & 1;
        const int kb = t * FK;
        if (t + 1 < nt) {
            load_tile(st ^ 1, kb + FK);
            asm volatile("cp.async.wait_group 1;\n");
        } else {
            asm volatile("cp.async.wait_group 0;\n");
        }
        __syncthreads();

        if (kb <= wlast) {
            const float* Kt = Ks + st * FK * LDS_STRIDE;
            const float* Vt = Vs + st * FK * LDS_STRIDE;

            float sacc[8][4];
            #pragma unroll
            for (int j = 0; j < 8; j++)
                #pragma unroll
                for (int c = 0; c < 4; c++) sacc[j][c] = 0.f;

            #pragma unroll
            for (int ks = 0; ks < 8; ks++) {
                #pragma unroll
                for (int jn = 0; jn < 8; jn++) {
                    int n = jn * 8 + grp;
                    uint32_t bf0 = f2tf32(Kt[n * LDS_STRIDE + ks * 8 + qid]);
                    uint32_t bf1 = f2tf32(Kt[n * LDS_STRIDE + ks * 8 + qid + 4]);
                    mma_tf32(sacc[jn][0], sacc[jn][1], sacc[jn][2], sacc[jn][3],
                             qf[ks][0], qf[ks][1], qf[ks][2], qf[ks][3], bf0, bf1);
                }
            }

            // causal mask: needed whenever the tile's last column can exceed
            // the warp's FIRST row.
            if (kb + FK - 1 > wrow0) {
                const int r0g = wrow0 + grp, r1g = wrow0 + grp + 8;
                #pragma unroll
                for (int jn = 0; jn < 8; jn++) {
                    int c0 = kb + jn * 8 + 2 * qid;
                    if (c0     > r0g) sacc[jn][0] = -1e30f;
                    if (c0 + 1 > r0g) sacc[jn][1] = -1e30f;
                    if (c0     > r1g) sacc[jn][2] = -1e30f;
                    if (c0 + 1 > r1g) sacc[jn][3] = -1e30f;
                }
            }

            float mt0 = -1e30f, mt1 = -1e30f;
            #pragma unroll
            for (int jn = 0; jn < 8; jn++) {
                mt0 = fmaxf(mt0, fmaxf(sacc[jn][0], sacc[jn][1]));
                mt1 = fmaxf(mt1, fmaxf(sacc[jn][2], sacc[jn][3]));
            }
            mt0 = fmaxf(mt0, __shfl_xor_sync(0xffffffffu, mt0, 1));
            mt0 = fmaxf(mt0, __shfl_xor_sync(0xffffffffu, mt0, 2));
            mt1 = fmaxf(mt1, __shfl_xor_sync(0xffffffffu, mt1, 1));
            mt1 = fmaxf(mt1, __shfl_xor_sync(0xffffffffu, mt1, 2));

            float mn0 = fmaxf(m0, mt0), mn1 = fmaxf(m1, mt1);
            float a0 = __expf(m0 - mn0), a1 = __expf(m1 - mn1);
            m0 = mn0; m1 = mn1;
            l0 *= a0; l1 *= a1;
            #pragma unroll
            for (int jn = 0; jn < 8; jn++) {
                oacc[jn][0] *= a0; oacc[jn][1] *= a0;
                oacc[jn][2] *= a1; oacc[jn][3] *= a1;
            }

            #pragma unroll
            for (int jn = 0; jn < 8; jn++) {
                float p00 = __uint_as_float(f2tf32(__expf(sacc[jn][0] - mn0)));
                float p01 = __uint_as_float(f2tf32(__expf(sacc[jn][1] - mn0)));
                float p10 = __uint_as_float(f2tf32(__expf(sacc[jn][2] - mn1)));
                float p11 = __uint_as_float(f2tf32(__expf(sacc[jn][3] - mn1)));
                l0 += p00 + p01;
                l1 += p10 + p11;
                int c = jn * 8 + 2 * qid;
                *reinterpret_cast<float2*>(&Pw[grp       * LDS_STRIDE + c]) =
                    make_float2(p00, p01);
                *reinterpret_cast<float2*>(&Pw[(grp + 8) * LDS_STRIDE + c]) =
                    make_float2(p10, p11);
            }
            __syncwarp();

            const uint32_t* Pu = reinterpret_cast<const uint32_t*>(Pw);
            #pragma unroll
            for (int ks = 0; ks < 8; ks++) {
                uint32_t af0 = Pu[grp       * LDS_STRIDE + ks * 8 + qid];
                uint32_t af1 = Pu[(grp + 8) * LDS_STRIDE + ks * 8 + qid];
                uint32_t af2 = Pu[grp       * LDS_STRIDE + ks * 8 + qid + 4];
                uint32_t af3 = Pu[(grp + 8) * LDS_STRIDE + ks * 8 + qid + 4];
                #pragma unroll
                for (int jn = 0; jn < 8; jn++) {
                    int n = jn * 8 + grp;
                    uint32_t bf0 = f2tf32(Vt[(ks * 8 + qid)     * LDS_STRIDE + n]);
                    uint32_t bf1 = f2tf32(Vt[(ks * 8 + qid + 4) * LDS_STRIDE + n]);
                    mma_tf32(oacc[jn][0], oacc[jn][1], oacc[jn][2], oacc[jn][3],
                             af0, af1, af2, af3, bf0, bf1);
                }
            }
        }
        __syncthreads();
    }

    l0 += __shfl_xor_sync(0xffffffffu, l0, 1);
    l0 += __shfl_xor_sync(0xffffffffu, l0, 2);
    l1 += __shfl_xor_sync(0xffffffffu, l1, 1);
    l1 += __shfl_xor_sync(0xffffffffu, l1, 2);
    const float inv0 = 1.f / l0, inv1 = 1.f / l1;

    float* Op = o + base + (size_t)wrow0 * D_MODEL;
    #pragma unroll
    for (int jn = 0; jn < 8; jn++) {
        int c = jn * 8 + 2 * qid;
        float2 o0 = make_float2(oacc[jn][0] * inv0, oacc[jn][1] * inv0);
        float2 o1 = make_float2(oacc[jn][2] * inv1, oacc[jn][3] * inv1);
        *reinterpret_cast<float2*>(&Op[(size_t)grp       * D_MODEL + c]) = o0;
        *reinterpret_cast<float2*>(&Op[(size_t)(grp + 8) * D_MODEL + c]) = o1;
    }
}

// ---------------------------------------------------------------------------
extern "C" void kernel_launch(void* const* d_in, const int* in_sizes, int n_in,
                              void* d_out, int out_size)
{
    const float* Q  = (const float*)d_in[0];
    const float* K  = (const float*)d_in[1];
    const float* V  = (const float*)d_in[2];
    const float* Wq = (const float*)d_in[3];
    const float* bq = (const float*)d_in[4];
    const float* Wk = (const float*)d_in[5];
    const float* bk = (const float*)d_in[6];
    const float* Wv = (const float*)d_in[7];
    const float* bv = (const float*)d_in[8];
    const float* Wo = (const float*)d_in[9];
    const float* bo = (const float*)d_in[10];
    float* out = (float*)d_out;

    float *qb, *kb, *vb, *ab;
    cudaGetSymbolAddress((void**)&qb, g_q);
    cudaGetSymbolAddress((void**)&kb, g_k);
    cudaGetSymbolAddress((void**)&vb, g_v);
    cudaGetSymbolAddress((void**)&ab, g_a);

    cudaFuncSetAttribute(flash_attn_tc_kernel,
                         cudaFuncAttributeMaxDynamicSharedMemorySize,
                         FLASH_SMEM_BYTES);

    dim3 qkv_grid(D_MODEL / BN, MROWS / BM, 3);
    gemm_tf32_kernel<<<qkv_grid, GTHREADS>>>(
        Q, Wq, bq, qb,
        K, Wk, bk, kb,
        V, Wv, bv, vb);

    flash_attn_tc_kernel<<<dim3(SEQ / FQ, NUM_HEAD, BATCH), 256,
                           FLASH_SMEM_BYTES>>>(qb, kb, vb, ab);

    dim3 o_grid(D_MODEL / BN, MROWS / BM, 1);
    gemm_tf32_kernel<<<o_grid, GTHREADS>>>(
        ab, Wo, bo, out,
        ab, Wo, bo, out,
        ab, Wo, bo, out);
}

// round 10
// speedup vs baseline: 1.0005x; 1.0005x over previous
#include <cuda_runtime.h>
#include <cstdint>

// ---------------------------------------------------------------------------
// MultiheadAttention  B=4, S=2048, D=1024, H=16, hd=64, causal, fp32.
// R9 = R8 resubmit (container infra failure):
//   GEMM warp tile 64x32 -> 64x64 (4 warps/CTA, 1.0 LDS+cvt per mma).
//   Flash attention kernel unchanged from R7 (972.8us baseline).
// ---------------------------------------------------------------------------

#define D_MODEL 1024
#define NUM_HEAD 16
#define HID_DIM 64
#define BATCH 4
#define SEQ 2048
#define MROWS (BATCH * SEQ)   // 8192

__device__ float g_q[(size_t)MROWS * D_MODEL];
__device__ float g_k[(size_t)MROWS * D_MODEL];
__device__ float g_v[(size_t)MROWS * D_MODEL];
__device__ float g_a[(size_t)MROWS * D_MODEL];

__device__ __forceinline__ uint32_t f2tf32(float f) {
    uint32_t r;
    asm volatile("cvt.rna.tf32.f32 %0, %1;" : "=r"(r) : "f"(f));
    return r;
}
__device__ __forceinline__ void cp_async16(uint32_t saddr, const void* gptr) {
    asm volatile("cp.async.cg.shared.global [%0], [%1], 16;\n" :: "r"(saddr), "l"(gptr));
}
__device__ __forceinline__ void cp_commit() {
    asm volatile("cp.async.commit_group;\n");
}
__device__ __forceinline__ void mma_tf32(
    float& d0, float& d1, float& d2, float& d3,
    uint32_t a0, uint32_t a1, uint32_t a2, uint32_t a3,
    uint32_t b0, uint32_t b1)
{
    asm volatile(
        "mma.sync.aligned.m16n8k8.row.col.f32.tf32.tf32.f32 "
        "{%0,%1,%2,%3}, {%4,%5,%6,%7}, {%8,%9}, {%0,%1,%2,%3};\n"
        : "+f"(d0), "+f"(d1), "+f"(d2), "+f"(d3)
        : "r"(a0), "r"(a1), "r"(a2), "r"(a3), "r"(b0), "r"(b1));
}

// ---------------------------------------------------------------------------
// tf32 GEMM: C[M,N] = A[M,K] @ W[N,K]^T + bias
// 128x128 CTA tile, BK=16, 128 threads (4 warps, 2x2), 64x64 warp tile.
// ---------------------------------------------------------------------------
#define BM 128
#define BN 128
#define BK 16
#define LDK 20
#define GTHREADS 128
#define KTILES (D_MODEL / BK)

__global__ __launch_bounds__(GTHREADS) void gemm_tf32_kernel(
    const float* __restrict__ A0, const float* __restrict__ W0,
    const float* __restrict__ b0, float* __restrict__ C0,
    const float* __restrict__ A1, const float* __restrict__ W1,
    const float* __restrict__ b1, float* __restrict__ C1,
    const float* __restrict__ A2, const float* __restrict__ W2,
    const float* __restrict__ b2, float* __restrict__ C2)
{
    __shared__ float As[2][BM][LDK];
    __shared__ float Ws[2][BN][LDK];

    const float* A; const float* W; const float* bias; float* C;
    if (blockIdx.z == 0)      { A = A0; W = W0; bias = b0; C = C0; }
    else if (blockIdx.z == 1) { A = A1; W = W1; bias = b1; C = C1; }
    else                      { A = A2; W = W2; bias = b2; C = C2; }

    const int tid  = threadIdx.x;
    const int row0 = blockIdx.y * BM;
    const int col0 = blockIdx.x * BN;
    const int K    = D_MODEL, N = D_MODEL;

    const int wid    = tid >> 5;
    const int lane   = tid & 31;
    const int warp_m = (wid & 1) * 64;   // 2 warps along M
    const int warp_n = (wid >> 1) * 64;  // 2 warps along N
    const int grp    = lane >> 2;
    const int qid    = lane & 3;
    const int lr     = tid >> 2;         // 0..31 (4 rows each: +0,32,64,96)
    const int lc     = (tid & 3) << 2;

    float acc[4][8][4];
    #pragma unroll
    for (int i = 0; i < 4; i++)
        #pragma unroll
        for (int j = 0; j < 8; j++)
            #pragma unroll
            for (int c = 0; c < 4; c++) acc[i][j][c] = 0.f;

    auto load_stage = [&](int st, int k0) {
        #pragma unroll
        for (int h = 0; h < 4; h++) {
            int r = lr + h * 32;
            cp_async16((uint32_t)__cvta_generic_to_shared(&As[st][r][lc]),
                       &A[(size_t)(row0 + r) * K + k0 + lc]);
            cp_async16((uint32_t)__cvta_generic_to_shared(&Ws[st][r][lc]),
                       &W[(size_t)(col0 + r) * K + k0 + lc]);
        }
        cp_commit();
    };

    load_stage(0, 0);

    for (int t = 0; t < KTILES; t++) {
        const int st = t & 1;
        if (t + 1 < KTILES) {
            load_stage(st ^ 1, (t + 1) * BK);
            asm volatile("cp.async.wait_group 1;\n");
        } else {
            asm volatile("cp.async.wait_group 0;\n");
        }
        __syncthreads();

        #pragma unroll
        for (int ks = 0; ks < BK; ks += 8) {
            uint32_t af[4][4], bf[8][2];
            #pragma unroll
            for (int i = 0; i < 4; i++) {
                int r = warp_m + i * 16 + grp;
                af[i][0] = f2tf32(As[st][r    ][ks + qid    ]);
                af[i][1] = f2tf32(As[st][r + 8][ks + qid    ]);
                af[i][2] = f2tf32(As[st][r    ][ks + qid + 4]);
                af[i][3] = f2tf32(As[st][r + 8][ks + qid + 4]);
            }
            #pragma unroll
            for (int j = 0; j < 8; j++) {
                int n = warp_n + j * 8 + grp;
                bf[j][0] = f2tf32(Ws[st][n][ks + qid    ]);
                bf[j][1] = f2tf32(Ws[st][n][ks + qid + 4]);
            }
            #pragma unroll
            for (int i = 0; i < 4; i++)
                #pragma unroll
                for (int j = 0; j < 8; j++)
                    mma_tf32(acc[i][j][0], acc[i][j][1], acc[i][j][2], acc[i][j][3],
                             af[i][0], af[i][1], af[i][2], af[i][3],
                             bf[j][0], bf[j][1]);
        }
        __syncthreads();
    }

    #pragma unroll
    for (int i = 0; i < 4; i++) {
        int r = row0 + warp_m + i * 16 + grp;
        #pragma unroll
        for (int j = 0; j < 8; j++) {
            int cidx = col0 + warp_n + j * 8 + qid * 2;
            float bx = bias[cidx], by = bias[cidx + 1];
            float2 o0 = make_float2(acc[i][j][0] + bx, acc[i][j][1] + by);
            float2 o1 = make_float2(acc[i][j][2] + bx, acc[i][j][3] + by);
            *reinterpret_cast<float2*>(&C[(size_t)r * N + cidx])       = o0;
            *reinterpret_cast<float2*>(&C[(size_t)(r + 8) * N + cidx]) = o1;
        }
    }
}

// ---------------------------------------------------------------------------
// Tensor-core flash attention (causal, tf32 mma).  Unchanged from R7.
// CTA: 256 threads = 8 warps; 128 q-rows per CTA, 16 per warp.
// ---------------------------------------------------------------------------
#define FQ 128
#define FK 64
#define LDS_STRIDE 68
#define KV_WORDS (2 * FK * LDS_STRIDE)
#define PS_WORDS (8 * 16 * LDS_STRIDE)
#define FLASH_SMEM_BYTES ((2 * KV_WORDS + PS_WORDS) * 4)   // 104448

__global__ __launch_bounds__(256, 1) void flash_attn_tc_kernel(
    const float* __restrict__ q, const float* __restrict__ k,
    const float* __restrict__ v, float* __restrict__ o)
{
    extern __shared__ float sm[];
    float* Ks = sm;                       // [2][FK][LDS_STRIDE]
    float* Vs = sm + KV_WORDS;            // [2][FK][LDS_STRIDE]
    float* Ps = sm + 2 * KV_WORDS;        // [8][16][LDS_STRIDE]

    const int qt  = blockIdx.x;
    const int h   = blockIdx.y;
    const int b   = blockIdx.z;
    const int tid = threadIdx.x;
    const int w   = tid >> 5;
    const int lane = tid & 31;
    const int grp = lane >> 2;
    const int qid = lane & 3;

    const int q0 = qt * FQ;
    const size_t base = (size_t)b * SEQ * D_MODEL + (size_t)h * HID_DIM;
    const int wrow0 = q0 + w * 16;
    const int wlast = wrow0 + 15;

    uint32_t qf[8][4];
    {
        const float* Qp = q + base + (size_t)wrow0 * D_MODEL;
        #pragma unroll
        for (int ks = 0; ks < 8; ks++) {
            int c = ks * 8 + qid;
            qf[ks][0] = f2tf32(0.125f * Qp[(size_t)grp       * D_MODEL + c]);
            qf[ks][1] = f2tf32(0.125f * Qp[(size_t)(grp + 8) * D_MODEL + c]);
            qf[ks][2] = f2tf32(0.125f * Qp[(size_t)grp       * D_MODEL + c + 4]);
            qf[ks][3] = f2tf32(0.125f * Qp[(size_t)(grp + 8) * D_MODEL + c + 4]);
        }
    }

    float oacc[8][4];
    #pragma unroll
    for (int j = 0; j < 8; j++)
        #pragma unroll
        for (int c = 0; c < 4; c++) oacc[j][c] = 0.f;
    float m0 = -1e30f, m1 = -1e30f, l0 = 0.f, l1 = 0.f;

    float* Pw = Ps + w * 16 * LDS_STRIDE;
    const int nt = 2 * (qt + 1);

    auto load_tile = [&](int st, int kb) {
        float* Kd = Ks + st * FK * LDS_STRIDE;
        float* Vd = Vs + st * FK * LDS_STRIDE;
        #pragma unroll
        for (int i = 0; i < 4; i++) {
            int idx = tid + (i << 8);
            int r   = idx >> 4;
            int c   = (idx & 15) << 2;
            const size_t goff = base + (size_t)(kb + r) * D_MODEL + c;
            cp_async16((uint32_t)__cvta_generic_to_shared(&Kd[r * LDS_STRIDE + c]), &k[goff]);
            cp_async16((uint32_t)__cvta_generic_to_shared(&Vd[r * LDS_STRIDE + c]), &v[goff]);
        }
        cp_commit();
    };

    load_tile(0, 0);

    for (int t = 0; t < nt; t++) {
        const int st = t & 1;
        const int kb = t * FK;
        if (t + 1 < nt) {
            load_tile(st ^ 1, kb + FK);
            asm volatile("cp.async.wait_group 1;\n");
        } else {
            asm volatile("cp.async.wait_group 0;\n");
        }
        __syncthreads();

        if (kb <= wlast) {
            const float* Kt = Ks + st * FK * LDS_STRIDE;
            const float* Vt = Vs + st * FK * LDS_STRIDE;

            float sacc[8][4];
            #pragma unroll
            for (int j = 0; j < 8; j++)
                #pragma unroll
                for (int c = 0; c < 4; c++) sacc[j][c] = 0.f;

            #pragma unroll
            for (int ks = 0; ks < 8; ks++) {
                #pragma unroll
                for (int jn = 0; jn < 8; jn++) {
                    int n = jn * 8 + grp;
                    uint32_t bf0 = f2tf32(Kt[n * LDS_STRIDE + ks * 8 + qid]);
                    uint32_t bf1 = f2tf32(Kt[n * LDS_STRIDE + ks * 8 + qid + 4]);
                    mma_tf32(sacc[jn][0], sacc[jn][1], sacc[jn][2], sacc[jn][3],
                             qf[ks][0], qf[ks][1], qf[ks][2], qf[ks][3], bf0, bf1);
                }
            }

            // causal mask: needed whenever the tile's last column can exceed
            // the warp's FIRST row.
            if (kb + FK - 1 > wrow0) {
                const int r0g = wrow0 + grp, r1g = wrow0 + grp + 8;
                #pragma unroll
                for (int jn = 0; jn < 8; jn++) {
                    int c0 = kb + jn * 8 + 2 * qid;
                    if (c0     > r0g) sacc[jn][0] = -1e30f;
                    if (c0 + 1 > r0g) sacc[jn][1] = -1e30f;
                    if (c0     > r1g) sacc[jn][2] = -1e30f;
                    if (c0 + 1 > r1g) sacc[jn][3] = -1e30f;
                }
            }

            float mt0 = -1e30f, mt1 = -1e30f;
            #pragma unroll
            for (int jn = 0; jn < 8; jn++) {
                mt0 = fmaxf(mt0, fmaxf(sacc[jn][0], sacc[jn][1]));
                mt1 = fmaxf(mt1, fmaxf(sacc[jn][2], sacc[jn][3]));
            }
            mt0 = fmaxf(mt0, __shfl_xor_sync(0xffffffffu, mt0, 1));
            mt0 = fmaxf(mt0, __shfl_xor_sync(0xffffffffu, mt0, 2));
            mt1 = fmaxf(mt1, __shfl_xor_sync(0xffffffffu, mt1, 1));
            mt1 = fmaxf(mt1, __shfl_xor_sync(0xffffffffu, mt1, 2));

            float mn0 = fmaxf(m0, mt0), mn1 = fmaxf(m1, mt1);
            float a0 = __expf(m0 - mn0), a1 = __expf(m1 - mn1);
            m0 = mn0; m1 = mn1;
            l0 *= a0; l1 *= a1;
            #pragma unroll
            for (int jn = 0; jn < 8; jn++) {
                oacc[jn][0] *= a0; oacc[jn][1] *= a0;
                oacc[jn][2] *= a1; oacc[jn][3] *= a1;
            }

            #pragma unroll
            for (int jn = 0; jn < 8; jn++) {
                float p00 = __uint_as_float(f2tf32(__expf(sacc[jn][0] - mn0)));
                float p01 = __uint_as_float(f2tf32(__expf(sacc[jn][1] - mn0)));
                float p10 = __uint_as_float(f2tf32(__expf(sacc[jn][2] - mn1)));
                float p11 = __uint_as_float(f2tf32(__expf(sacc[jn][3] - mn1)));
                l0 += p00 + p01;
                l1 += p10 + p11;
                int c = jn * 8 + 2 * qid;
                *reinterpret_cast<float2*>(&Pw[grp       * LDS_STRIDE + c]) =
                    make_float2(p00, p01);
                *reinterpret_cast<float2*>(&Pw[(grp + 8) * LDS_STRIDE + c]) =
                    make_float2(p10, p11);
            }
            __syncwarp();

            const uint32_t* Pu = reinterpret_cast<const uint32_t*>(Pw);
            #pragma unroll
            for (int ks = 0; ks < 8; ks++) {
                uint32_t af0 = Pu[grp       * LDS_STRIDE + ks * 8 + qid];
                uint32_t af1 = Pu[(grp + 8) * LDS_STRIDE + ks * 8 + qid];
                uint32_t af2 = Pu[grp       * LDS_STRIDE + ks * 8 + qid + 4];
                uint32_t af3 = Pu[(grp + 8) * LDS_STRIDE + ks * 8 + qid + 4];
                #pragma unroll
                for (int jn = 0; jn < 8; jn++) {
                    int n = jn * 8 + grp;
                    uint32_t bf0 = f2tf32(Vt[(ks * 8 + qid)     * LDS_STRIDE + n]);
                    uint32_t bf1 = f2tf32(Vt[(ks * 8 + qid + 4) * LDS_STRIDE + n]);
                    mma_tf32(oacc[jn][0], oacc[jn][1], oacc[jn][2], oacc[jn][3],
                             af0, af1, af2, af3, bf0, bf1);
                }
            }
        }
        __syncthreads();
    }

    l0 += __shfl_xor_sync(0xffffffffu, l0, 1);
    l0 += __shfl_xor_sync(0xffffffffu, l0, 2);
    l1 += __shfl_xor_sync(0xffffffffu, l1, 1);
    l1 += __shfl_xor_sync(0xffffffffu, l1, 2);
    const float inv0 = 1.f / l0, inv1 = 1.f / l1;

    float* Op = o + base + (size_t)wrow0 * D_MODEL;
    #pragma unroll
    for (int jn = 0; jn < 8; jn++) {
        int c = jn * 8 + 2 * qid;
        float2 o0 = make_float2(oacc[jn][0] * inv0, oacc[jn][1] * inv0);
        float2 o1 = make_float2(oacc[jn][2] * inv1, oacc[jn][3] * inv1);
        *reinterpret_cast<float2*>(&Op[(size_t)grp       * D_MODEL + c]) = o0;
        *reinterpret_cast<float2*>(&Op[(size_t)(grp + 8) * D_MODEL + c]) = o1;
    }
}

// ---------------------------------------------------------------------------
extern "C" void kernel_launch(void* const* d_in, const int* in_sizes, int n_in,
                              void* d_out, int out_size)
{
    const float* Q  = (const float*)d_in[0];
    const float* K  = (const float*)d_in[1];
    const float* V  = (const float*)d_in[2];
    const float* Wq = (const float*)d_in[3];
    const float* bq = (const float*)d_in[4];
    const float* Wk = (const float*)d_in[5];
    const float* bk = (const float*)d_in[6];
    const float* Wv = (const float*)d_in[7];
    const float* bv = (const float*)d_in[8];
    const float* Wo = (const float*)d_in[9];
    const float* bo = (const float*)d_in[10];
    float* out = (float*)d_out;

    float *qb, *kb, *vb, *ab;
    cudaGetSymbolAddress((void**)&qb, g_q);
    cudaGetSymbolAddress((void**)&kb, g_k);
    cudaGetSymbolAddress((void**)&vb, g_v);
    cudaGetSymbolAddress((void**)&ab, g_a);

    cudaFuncSetAttribute(flash_attn_tc_kernel,
                         cudaFuncAttributeMaxDynamicSharedMemorySize,
                         FLASH_SMEM_BYTES);

    dim3 qkv_grid(D_MODEL / BN, MROWS / BM, 3);
    gemm_tf32_kernel<<<qkv_grid, GTHREADS>>>(
        Q, Wq, bq, qb,
        K, Wk, bk, kb,
        V, Wv, bv, vb);

    flash_attn_tc_kernel<<<dim3(SEQ / FQ, NUM_HEAD, BATCH), 256,
                           FLASH_SMEM_BYTES>>>(qb, kb, vb, ab);

    dim3 o_grid(D_MODEL / BN, MROWS / BM, 1);
    gemm_tf32_kernel<<<o_grid, GTHREADS>>>(
        ab, Wo, bo, out,
        ab, Wo, bo, out,
        ab, Wo, bo, out);
}